// round 12
// baseline (speedup 1.0000x reference)
#include <cuda_runtime.h>
#include <cuda_fp16.h>
#include <cstdint>

#define N_DIM 16384
#define D_DIM 10240
#define C_DIM 128
#define NUM_CHUNK 160           // chunks of 64 k
#define NUM_KSTEP 640           // k16 steps
#define THREADS 256

// Device-resolved input bindings (selector kernel writes these).
__device__ const float* g_x;
__device__ const float* g_am;

// am repacked to fp16 in MMA B-fragment slot order:
// slot index (g*128 + c)*4 + lt  holds fp16 {k, k+1, k+8, k+9} of class c,
// where k = g*16 + lt*2.  (uint2 = 8 bytes per slot; 2.6 MB total)
__device__ uint2 g_bm[(size_t)NUM_KSTEP * C_DIM * 4];

__global__ void select_inputs_kernel(const float* a, const float* b) {
    bool a_is_am = true;
    for (int i = 0; i < 64; ++i) {
        float v = a[i];
        if (v != 1.0f && v != -1.0f) { a_is_am = false; break; }
    }
    g_x  = a_is_am ? b : a;
    g_am = a_is_am ? a : b;
}

static __device__ __forceinline__ uint32_t f16x2_rn(float2 v) {
    __half2 h2 = __float22half2_rn(v);
    return reinterpret_cast<uint32_t&>(h2);
}
// 2-way exact split of a float2 into f16x2 hi/mid; residual <= 2^-23 |x|
static __device__ __forceinline__ void split2(float2 v, uint32_t& h, uint32_t& m) {
    __half2 h2 = __float22half2_rn(v);
    float2 hf = __half22float2(h2);
    __half2 m2 = __float22half2_rn(make_float2(v.x - hf.x, v.y - hf.y));
    h = reinterpret_cast<uint32_t&>(h2);
    m = reinterpret_cast<uint32_t&>(m2);
}

// Pack am (+/-1, fp16-exact) into fragment-slot layout. 327680 threads.
__global__ void am_pack_kernel() {
    const float* am = g_am;
    int tid = blockIdx.x * blockDim.x + threadIdx.x;   // 0 .. 640*128*4-1
    int g  = tid >> 9;          // kstep
    int r  = tid & 511;
    int c  = r >> 2;            // class
    int lt = r & 3;
    const float* s = am + (size_t)c * D_DIM + g * 16 + lt * 2;
    float2 v0 = *(const float2*)s;         // k, k+1
    float2 v1 = *(const float2*)(s + 8);   // k+8, k+9
    g_bm[tid] = make_uint2(f16x2_rn(v0), f16x2_rn(v1));
}

#define MMA16816(d, a0_, a1_, a2_, a3_, b0_, b1_)                                 \
    asm volatile("mma.sync.aligned.m16n8k16.row.col.f32.f16.f16.f32 "             \
                 "{%0,%1,%2,%3}, {%4,%5,%6,%7}, {%8,%9}, {%0,%1,%2,%3};"          \
                 : "+f"((d)[0]), "+f"((d)[1]), "+f"((d)[2]), "+f"((d)[3])         \
                 : "r"(a0_), "r"(a1_), "r"(a2_), "r"(a3_), "r"(b0_), "r"(b1_))

// Load the 16 B fragment pairs for kstep g into br[32] (coalesced LDG.64.NC).
#define LOAD_B(br, g_)                                                            \
    do {                                                                          \
        const uint2* bp_ = g_bm + ((size_t)(g_) << 9) + boff;                     \
        _Pragma("unroll")                                                         \
        for (int n_ = 0; n_ < 16; ++n_) {                                         \
            uint2 t_ = __ldg(bp_ + n_ * 32);                                      \
            (br)[2 * n_] = t_.x;                                                  \
            (br)[2 * n_ + 1] = t_.y;                                              \
        }                                                                         \
    } while (0)

__global__ void __launch_bounds__(THREADS, 1)
hd_mma_kernel(float* __restrict__ out) {
    const float* __restrict__ x = g_x;

    const int tid = threadIdx.x;
    const int w = tid >> 5, l = tid & 31;
    const int lg = l >> 2;        // lane group = row within m16 tile (PTX A frag)
    const int lt = l & 3;         // thread in group (PTX A frag)

    // ---- A: direct-gmem fragment pointers (PTX m16n8k16 A layout) ----
    const float* pr0 = x + ((size_t)blockIdx.x * 128 + w * 16 + lg) * D_DIM + lt * 2;
    const float* pr8 = pr0 + (size_t)8 * D_DIM;

    // ---- B: per-lane slot offset within a kstep block (512 slots/kstep) ----
    const int boff = lg * 4 + lt;          // + n*32 per n-tile

    float acc[16][4];
#pragma unroll
    for (int n = 0; n < 16; ++n)
#pragma unroll
        for (int e = 0; e < 4; ++e) acc[n][e] = 0.0f;

    // A register prefetch: full chunk (4 ksteps x 4 fragments), refilled in place.
    float2 va[4][4];
#pragma unroll
    for (int j = 0; j < 4; ++j) {
        const int off = j * 16;
        va[j][0] = *(const float2*)(pr0 + off);
        va[j][1] = *(const float2*)(pr8 + off);
        va[j][2] = *(const float2*)(pr0 + off + 8);
        va[j][3] = *(const float2*)(pr8 + off + 8);
    }

    // B ping-pong: breg[j&1] is current, prefetch next kstep into the other.
    uint32_t breg[2][32];
    LOAD_B(breg[0], 0);

    for (int ch = 0; ch < NUM_CHUNK; ++ch) {
        const bool more = (ch + 1 < NUM_CHUNK);
#pragma unroll
        for (int j = 0; j < 4; ++j) {
            const int g = ch * 4 + j;
            uint32_t* bcur = breg[j & 1];
            uint32_t* bnxt = breg[(j + 1) & 1];

            // Prefetch B for kstep g+1 (L1-resident after first warp touches it)
            if (j < 3) {
                LOAD_B(bnxt, g + 1);
            } else if (more) {
                LOAD_B(bnxt, g + 1);
            }

            // Split current A fragments
            uint32_t ah[4], amd[4];
            split2(va[j][0], ah[0], amd[0]);
            split2(va[j][1], ah[1], amd[1]);
            split2(va[j][2], ah[2], amd[2]);
            split2(va[j][3], ah[3], amd[3]);

            // Refill va[j] from next chunk (load->use distance = 4 ksteps)
            if (more) {
                const int off = (ch + 1) * 64 + j * 16;
                va[j][0] = *(const float2*)(pr0 + off);
                va[j][1] = *(const float2*)(pr8 + off);
                va[j][2] = *(const float2*)(pr0 + off + 8);
                va[j][3] = *(const float2*)(pr8 + off + 8);
            }

            // split-outer / n-inner: consecutive MMAs hit distinct accumulators
#pragma unroll
            for (int n = 0; n < 16; ++n)
                MMA16816(acc[n], ah[0], ah[1], ah[2], ah[3], bcur[2 * n], bcur[2 * n + 1]);
#pragma unroll
            for (int n = 0; n < 16; ++n)
                MMA16816(acc[n], amd[0], amd[1], amd[2], amd[3], bcur[2 * n], bcur[2 * n + 1]);
        }
    }

    // ---- epilogue: per-row first-max argmax over 128 classes ----
    // acc[n][e]: row = w*16 + (e<2 ? lg : lg+8), col = n*8 + lt*2 + (e&1)
#pragma unroll
    for (int h = 0; h < 2; ++h) {
        float best = -3.402823466e38f;
        int bi = 0;
#pragma unroll
        for (int n = 0; n < 16; ++n)
#pragma unroll
            for (int e = 0; e < 2; ++e) {
                float v = acc[n][h * 2 + e];
                int c = n * 8 + lt * 2 + e;
                if (v > best) { best = v; bi = c; }
            }
#pragma unroll
        for (int ofs = 1; ofs < 4; ofs <<= 1) {
            float ov = __shfl_xor_sync(0xffffffffu, best, ofs);
            int oi = __shfl_xor_sync(0xffffffffu, bi, ofs);
            if (ov > best || (ov == best && oi < bi)) { best = ov; bi = oi; }
        }
        if (lt == 0)
            out[blockIdx.x * 128 + w * 16 + h * 8 + lg] = (float)bi;  // float32 output
    }
}

extern "C" void kernel_launch(void* const* d_in, const int* in_sizes, int n_in,
                              void* d_out, int out_size) {
    const float* a = (const float*)d_in[0];
    const float* b = (const float*)d_in[1];

    select_inputs_kernel<<<1, 1>>>(a, b);
    am_pack_kernel<<<(NUM_KSTEP * C_DIM * 4) / 256, 256>>>();
    hd_mma_kernel<<<N_DIM / 128, THREADS>>>((float*)d_out);
}